// round 2
// baseline (speedup 1.0000x reference)
#include <cuda_runtime.h>
#include <cstddef>

#define N_WORD 50000
#define N_DOC  50000
#define D      128

// ---------------------------------------------------------------------------
// Scratch: per-etype segment sums (raw-h aggregation) + in-degrees.
// mean_agg(hW^T+b) == (segsum(h[src])/max(deg,1)) W^T + [deg>0]*b
// ---------------------------------------------------------------------------
__device__ float g_sum_ww[(size_t)N_WORD * D];
__device__ float g_sum_dw[(size_t)N_WORD * D];
__device__ float g_sum_wd[(size_t)N_DOC  * D];
__device__ int   g_deg_ww[N_WORD];
__device__ int   g_deg_dw[N_WORD];
__device__ int   g_deg_wd[N_DOC];

// ---------------------------------------------------------------------------
// Zero the accumulators (scratch must be reset every call: deterministic work)
// ---------------------------------------------------------------------------
__global__ void zero_kernel() {
    int i = blockIdx.x * blockDim.x + threadIdx.x;
    float4 z = make_float4(0.f, 0.f, 0.f, 0.f);
    if (i < N_WORD * D / 4) {
        reinterpret_cast<float4*>(g_sum_ww)[i] = z;
        reinterpret_cast<float4*>(g_sum_dw)[i] = z;
        reinterpret_cast<float4*>(g_sum_wd)[i] = z;
    }
    if (i < N_WORD) {
        g_deg_ww[i] = 0;
        g_deg_dw[i] = 0;
        g_deg_wd[i] = 0;
    }
}

// ---------------------------------------------------------------------------
// Edge scatter: warp-per-edge iteration; each lane handles 4 consecutive
// floats (float4 gather from L2-resident h, 4 coalesced fp32 REDs).
// Edge indices staged in smem, broadcast-read per warp.
// ---------------------------------------------------------------------------
__global__ __launch_bounds__(256) void scatter_kernel(
    const float* __restrict__ h,
    const int*   __restrict__ src,
    const int*   __restrict__ dst,
    float*       __restrict__ sum,
    int*         __restrict__ deg,
    int E)
{
    __shared__ int s_src[256];
    __shared__ int s_dst[256];
    int tid  = threadIdx.x;
    int base = blockIdx.x * 256;
    int e    = base + tid;
    s_src[tid] = (e < E) ? src[e] : -1;
    s_dst[tid] = (e < E) ? dst[e] : 0;
    __syncthreads();

    int lane = tid & 31;
    int w0   = (tid >> 5) * 32;

    for (int j = 0; j < 32; j++) {
        int s = s_src[w0 + j];          // broadcast LDS
        if (s >= 0) {
            int d = s_dst[w0 + j];
            float4 v = reinterpret_cast<const float4*>(h + (size_t)s * D)[lane];
            float* o = sum + (size_t)d * D + lane * 4;
            atomicAdd(o + 0, v.x);      // result unused -> RED
            atomicAdd(o + 1, v.y);
            atomicAdd(o + 2, v.z);
            atomicAdd(o + 3, v.w);
            if (lane == 0) atomicAdd(&deg[d], 1);
        }
    }
}

// ---------------------------------------------------------------------------
// Fused GEMM epilogue for word outputs:
//   out = relu(A_ww W_ww^T + m_ww*b_ww + A_dw W_dw^T + m_dw*b_dw)
// Block: 64 rows x 128 cols, 256 threads (8 warps x 32 lanes).
// Thread: 8 rows x 4 cols of accumulators. Both 128x128 W matrices live in
// smem transposed (Wt[k][j], row pad 132 -> conflict-free float4 reads).
// A-tile reads are warp-broadcast LDS.
// ---------------------------------------------------------------------------
#define WT_PITCH 132
#define SMEM_WORD_FLOATS (2 * 128 * WT_PITCH + 2 * 64 * 128 + 256)
#define SMEM_DOC_FLOATS  (128 * WT_PITCH + 64 * 128 + 128)

__global__ __launch_bounds__(256) void gemm_word_kernel(
    const float* __restrict__ W1, const float* __restrict__ b1g,
    const float* __restrict__ W2, const float* __restrict__ b2g,
    float* __restrict__ out)
{
    extern __shared__ float sm[];
    float* Wt1 = sm;                       // 128 * 132
    float* Wt2 = Wt1 + 128 * WT_PITCH;
    float* A1  = Wt2 + 128 * WT_PITCH;     // 64 * 128
    float* A2  = A1 + 64 * 128;
    float* rd1 = A2 + 64 * 128;            // 64
    float* rd2 = rd1 + 64;
    float* m1s = rd2 + 64;
    float* m2s = m1s + 64;

    int tid  = threadIdx.x;
    int lane = tid & 31;
    int wr   = tid >> 5;
    int row0 = blockIdx.x * 64;

    if (tid < 64) {
        int row = row0 + tid;
        int d1 = (row < N_WORD) ? g_deg_ww[row] : 0;
        int d2 = (row < N_WORD) ? g_deg_dw[row] : 0;
        rd1[tid] = d1 > 0 ? 1.0f / (float)d1 : 0.f;
        rd2[tid] = d2 > 0 ? 1.0f / (float)d2 : 0.f;
        m1s[tid] = d1 > 0 ? 1.f : 0.f;
        m2s[tid] = d2 > 0 ? 1.f : 0.f;
    }
    // W transpose into smem (coalesced global reads; one-time STS conflicts OK)
    for (int idx = tid; idx < 128 * 128; idx += 256) {
        int j = idx >> 7, k = idx & 127;
        Wt1[k * WT_PITCH + j] = W1[idx];
        Wt2[k * WT_PITCH + j] = W2[idx];
    }
    __syncthreads();
    // normalized A tiles
    for (int idx = tid; idx < 64 * 128; idx += 256) {
        int r = idx >> 7;
        int row = row0 + r;
        float v1 = 0.f, v2 = 0.f;
        if (row < N_WORD) {
            int k = idx & 127;
            v1 = g_sum_ww[(size_t)row * D + k] * rd1[r];
            v2 = g_sum_dw[(size_t)row * D + k] * rd2[r];
        }
        A1[idx] = v1;
        A2[idx] = v2;
    }
    __syncthreads();

    float acc[8][4];
    #pragma unroll
    for (int i = 0; i < 8; i++)
        #pragma unroll
        for (int c = 0; c < 4; c++) acc[i][c] = 0.f;

    const float* Ap = A1 + wr * 8 * 128;
    const float* Wp = Wt1;
    #pragma unroll 1
    for (int pass = 0; pass < 2; pass++) {
        #pragma unroll 2
        for (int k = 0; k < 128; k += 4) {
            float4 b0 = *reinterpret_cast<const float4*>(&Wp[(k + 0) * WT_PITCH + lane * 4]);
            float4 b1 = *reinterpret_cast<const float4*>(&Wp[(k + 1) * WT_PITCH + lane * 4]);
            float4 b2 = *reinterpret_cast<const float4*>(&Wp[(k + 2) * WT_PITCH + lane * 4]);
            float4 b3 = *reinterpret_cast<const float4*>(&Wp[(k + 3) * WT_PITCH + lane * 4]);
            #pragma unroll
            for (int i = 0; i < 8; i++) {
                float4 a = *reinterpret_cast<const float4*>(&Ap[i * 128 + k]); // broadcast
                acc[i][0] += a.x * b0.x + a.y * b1.x + a.z * b2.x + a.w * b3.x;
                acc[i][1] += a.x * b0.y + a.y * b1.y + a.z * b2.y + a.w * b3.y;
                acc[i][2] += a.x * b0.z + a.y * b1.z + a.z * b2.z + a.w * b3.z;
                acc[i][3] += a.x * b0.w + a.y * b1.w + a.z * b2.w + a.w * b3.w;
            }
        }
        Ap = A2 + wr * 8 * 128;
        Wp = Wt2;
    }

    float4 bias1 = *reinterpret_cast<const float4*>(&b1g[lane * 4]);
    float4 bias2 = *reinterpret_cast<const float4*>(&b2g[lane * 4]);
    #pragma unroll
    for (int i = 0; i < 8; i++) {
        int r = wr * 8 + i;
        int row = row0 + r;
        if (row < N_WORD) {
            float mm1 = m1s[r], mm2 = m2s[r];
            float4 o;
            o.x = fmaxf(acc[i][0] + mm1 * bias1.x + mm2 * bias2.x, 0.f);
            o.y = fmaxf(acc[i][1] + mm1 * bias1.y + mm2 * bias2.y, 0.f);
            o.z = fmaxf(acc[i][2] + mm1 * bias1.z + mm2 * bias2.z, 0.f);
            o.w = fmaxf(acc[i][3] + mm1 * bias1.w + mm2 * bias2.w, 0.f);
            *reinterpret_cast<float4*>(&out[(size_t)row * D + lane * 4]) = o;
        }
    }
}

__global__ __launch_bounds__(256) void gemm_doc_kernel(
    const float* __restrict__ W1, const float* __restrict__ b1g,
    float* __restrict__ out)
{
    extern __shared__ float sm[];
    float* Wt1 = sm;                       // 128 * 132
    float* A1  = Wt1 + 128 * WT_PITCH;     // 64 * 128
    float* rd1 = A1 + 64 * 128;            // 64
    float* m1s = rd1 + 64;

    int tid  = threadIdx.x;
    int lane = tid & 31;
    int wr   = tid >> 5;
    int row0 = blockIdx.x * 64;

    if (tid < 64) {
        int row = row0 + tid;
        int d1 = (row < N_DOC) ? g_deg_wd[row] : 0;
        rd1[tid] = d1 > 0 ? 1.0f / (float)d1 : 0.f;
        m1s[tid] = d1 > 0 ? 1.f : 0.f;
    }
    for (int idx = tid; idx < 128 * 128; idx += 256) {
        int j = idx >> 7, k = idx & 127;
        Wt1[k * WT_PITCH + j] = W1[idx];
    }
    __syncthreads();
    for (int idx = tid; idx < 64 * 128; idx += 256) {
        int r = idx >> 7;
        int row = row0 + r;
        float v1 = 0.f;
        if (row < N_DOC) {
            int k = idx & 127;
            v1 = g_sum_wd[(size_t)row * D + k] * rd1[r];
        }
        A1[idx] = v1;
    }
    __syncthreads();

    float acc[8][4];
    #pragma unroll
    for (int i = 0; i < 8; i++)
        #pragma unroll
        for (int c = 0; c < 4; c++) acc[i][c] = 0.f;

    const float* Ap = A1 + wr * 8 * 128;
    #pragma unroll 2
    for (int k = 0; k < 128; k += 4) {
        float4 b0 = *reinterpret_cast<const float4*>(&Wt1[(k + 0) * WT_PITCH + lane * 4]);
        float4 b1 = *reinterpret_cast<const float4*>(&Wt1[(k + 1) * WT_PITCH + lane * 4]);
        float4 b2 = *reinterpret_cast<const float4*>(&Wt1[(k + 2) * WT_PITCH + lane * 4]);
        float4 b3 = *reinterpret_cast<const float4*>(&Wt1[(k + 3) * WT_PITCH + lane * 4]);
        #pragma unroll
        for (int i = 0; i < 8; i++) {
            float4 a = *reinterpret_cast<const float4*>(&Ap[i * 128 + k]);
            acc[i][0] += a.x * b0.x + a.y * b1.x + a.z * b2.x + a.w * b3.x;
            acc[i][1] += a.x * b0.y + a.y * b1.y + a.z * b2.y + a.w * b3.y;
            acc[i][2] += a.x * b0.z + a.y * b1.z + a.z * b2.z + a.w * b3.z;
            acc[i][3] += a.x * b0.w + a.y * b1.w + a.z * b2.w + a.w * b3.w;
        }
    }

    float4 bias1 = *reinterpret_cast<const float4*>(&b1g[lane * 4]);
    #pragma unroll
    for (int i = 0; i < 8; i++) {
        int r = wr * 8 + i;
        int row = row0 + r;
        if (row < N_DOC) {
            float mm1 = m1s[r];
            float4 o;
            o.x = fmaxf(acc[i][0] + mm1 * bias1.x, 0.f);
            o.y = fmaxf(acc[i][1] + mm1 * bias1.y, 0.f);
            o.z = fmaxf(acc[i][2] + mm1 * bias1.z, 0.f);
            o.w = fmaxf(acc[i][3] + mm1 * bias1.w, 0.f);
            *reinterpret_cast<float4*>(&out[(size_t)row * D + lane * 4]) = o;
        }
    }
}

// ---------------------------------------------------------------------------
// Launch
// ---------------------------------------------------------------------------
extern "C" void kernel_launch(void* const* d_in, const int* in_sizes, int n_in,
                              void* d_out, int out_size)
{
    const float* h_word = (const float*)d_in[0];
    const float* h_doc  = (const float*)d_in[1];
    const float* W_ww   = (const float*)d_in[2];
    const float* b_ww   = (const float*)d_in[3];
    const float* W_wd   = (const float*)d_in[4];
    const float* b_wd   = (const float*)d_in[5];
    const float* W_dw   = (const float*)d_in[6];
    const float* b_dw   = (const float*)d_in[7];
    const int* src_ww = (const int*)d_in[8];
    const int* dst_ww = (const int*)d_in[9];
    const int* src_wd = (const int*)d_in[10];
    const int* dst_wd = (const int*)d_in[11];
    const int* src_dw = (const int*)d_in[12];
    const int* dst_dw = (const int*)d_in[13];
    float* out = (float*)d_out;

    int E_ww = in_sizes[8];
    int E_wd = in_sizes[10];
    int E_dw = in_sizes[12];

    // resolve scratch symbol addresses (immediate host-side queries; no allocs)
    float *p_sww, *p_sdw, *p_swd;
    int   *p_dww, *p_ddw, *p_dwd;
    cudaGetSymbolAddress((void**)&p_sww, g_sum_ww);
    cudaGetSymbolAddress((void**)&p_sdw, g_sum_dw);
    cudaGetSymbolAddress((void**)&p_swd, g_sum_wd);
    cudaGetSymbolAddress((void**)&p_dww, g_deg_ww);
    cudaGetSymbolAddress((void**)&p_ddw, g_deg_dw);
    cudaGetSymbolAddress((void**)&p_dwd, g_deg_wd);

    size_t smem_word = SMEM_WORD_FLOATS * sizeof(float);
    size_t smem_doc  = SMEM_DOC_FLOATS  * sizeof(float);
    cudaFuncSetAttribute(gemm_word_kernel, cudaFuncAttributeMaxDynamicSharedMemorySize, (int)smem_word);
    cudaFuncSetAttribute(gemm_doc_kernel,  cudaFuncAttributeMaxDynamicSharedMemorySize, (int)smem_doc);

    zero_kernel<<<(N_WORD * D / 4 + 255) / 256, 256>>>();

    scatter_kernel<<<(E_ww + 255) / 256, 256>>>(h_word, src_ww, dst_ww, p_sww, p_dww, E_ww);
    scatter_kernel<<<(E_dw + 255) / 256, 256>>>(h_doc,  src_dw, dst_dw, p_sdw, p_ddw, E_dw);
    scatter_kernel<<<(E_wd + 255) / 256, 256>>>(h_word, src_wd, dst_wd, p_swd, p_dwd, E_wd);

    gemm_word_kernel<<<(N_WORD + 63) / 64, 256, smem_word>>>(W_ww, b_ww, W_dw, b_dw, out);
    gemm_doc_kernel<<<(N_DOC + 63) / 64, 256, smem_doc>>>(W_wd, b_wd, out + (size_t)N_WORD * D);
}

// round 3
// speedup vs baseline: 2.4524x; 2.4524x over previous
#include <cuda_runtime.h>
#include <cstddef>

#define N_WORD 50000
#define N_DOC  50000
#define D      128
#define NSEG   150000          // seg0: ww->word, seg1: dw->word, seg2: wd->doc
#define EMAX   1900000         // >= 3*E
#define SCAN_B 512
#define NBLK_SCAN ((NSEG + SCAN_B - 1) / SCAN_B)   // 293

// ---------------------------------------------------------------------------
// Scratch
// ---------------------------------------------------------------------------
__device__ int   g_counts[NSEG];
__device__ int   g_scan_local[NSEG];     // exclusive within scan block
__device__ int   g_blocksum[NBLK_SCAN];
__device__ int   g_blockoff[NBLK_SCAN];
__device__ int   g_row_ptr[NSEG + 1];
__device__ int   g_cursor[NSEG];
__device__ int   g_epos[EMAX];           // src node id per CSR slot
__device__ float g_mean[(size_t)NSEG * D];
__device__ int   g_deg[NSEG];

// ---------------------------------------------------------------------------
// 1) zero counters
// ---------------------------------------------------------------------------
__global__ void zero_counts_kernel() {
    int i = blockIdx.x * blockDim.x + threadIdx.x;
    if (i < NSEG) g_counts[i] = 0;
}

// ---------------------------------------------------------------------------
// 2) histogram of dst per etype segment
// ---------------------------------------------------------------------------
__global__ __launch_bounds__(512) void hist_kernel(const int* __restrict__ dst,
                                                   int E, int segbase) {
    int i = blockIdx.x * blockDim.x + threadIdx.x;
    if (i < E) atomicAdd(&g_counts[segbase + dst[i]], 1);
}

// ---------------------------------------------------------------------------
// 3) two-level exclusive scan over g_counts -> g_row_ptr
// ---------------------------------------------------------------------------
__global__ __launch_bounds__(SCAN_B) void scan_block_kernel() {
    __shared__ int sm[SCAN_B];
    int b = blockIdx.x, t = threadIdx.x;
    int gi = b * SCAN_B + t;
    int v = (gi < NSEG) ? g_counts[gi] : 0;
    sm[t] = v;
    __syncthreads();
    // Hillis-Steele inclusive
    #pragma unroll
    for (int off = 1; off < SCAN_B; off <<= 1) {
        int x = (t >= off) ? sm[t - off] : 0;
        __syncthreads();
        sm[t] += x;
        __syncthreads();
    }
    if (gi < NSEG) g_scan_local[gi] = sm[t] - v;   // exclusive
    if (t == SCAN_B - 1) g_blocksum[b] = sm[t];
}

__global__ __launch_bounds__(SCAN_B) void scan_top_kernel() {
    __shared__ int sm[SCAN_B];
    int t = threadIdx.x;
    int v = (t < NBLK_SCAN) ? g_blocksum[t] : 0;
    sm[t] = v;
    __syncthreads();
    #pragma unroll
    for (int off = 1; off < SCAN_B; off <<= 1) {
        int x = (t >= off) ? sm[t - off] : 0;
        __syncthreads();
        sm[t] += x;
        __syncthreads();
    }
    if (t < NBLK_SCAN) g_blockoff[t] = sm[t] - v;  // exclusive
}

__global__ void scan_finish_kernel(int Etot) {
    int i = blockIdx.x * blockDim.x + threadIdx.x;
    if (i < NSEG) {
        int v = g_scan_local[i] + g_blockoff[i / SCAN_B];
        g_row_ptr[i] = v;
        g_cursor[i]  = v;
    }
    if (i == 0) g_row_ptr[NSEG] = Etot;
}

// ---------------------------------------------------------------------------
// 4) fill CSR edge positions with src ids
// ---------------------------------------------------------------------------
__global__ __launch_bounds__(512) void fill_kernel(const int* __restrict__ src,
                                                   const int* __restrict__ dst,
                                                   int E, int segbase) {
    int i = blockIdx.x * blockDim.x + threadIdx.x;
    if (i < E) {
        int p = atomicAdd(&g_cursor[segbase + dst[i]], 1);
        g_epos[p] = src[i];
    }
}

// ---------------------------------------------------------------------------
// 5) warp-per-dst gather-reduce; writes mean directly (no atomics, no zeroing)
// seg0 (rows 0..49999):        gather from h_word
// seg1 (rows 50000..99999):    gather from h_doc
// seg2 (rows 100000..149999):  gather from h_word
// ---------------------------------------------------------------------------
__global__ __launch_bounds__(256) void agg_kernel(const float* __restrict__ h_word,
                                                  const float* __restrict__ h_doc) {
    int warp = (blockIdx.x * blockDim.x + threadIdx.x) >> 5;
    int lane = threadIdx.x & 31;
    if (warp >= NSEG) return;

    const float* h = (warp >= N_WORD && warp < 2 * N_WORD) ? h_doc : h_word;

    int start = g_row_ptr[warp];
    int end   = g_row_ptr[warp + 1];
    int deg   = end - start;

    float4 acc = make_float4(0.f, 0.f, 0.f, 0.f);
    for (int base = start; base < end; base += 32) {
        int n = min(32, end - base);
        int myidx = (lane < n) ? g_epos[base + lane] : 0;   // coalesced
        for (int j = 0; j < n; j++) {
            int s = __shfl_sync(0xFFFFFFFFu, myidx, j);
            float4 v = reinterpret_cast<const float4*>(h + (size_t)s * D)[lane];
            acc.x += v.x; acc.y += v.y; acc.z += v.z; acc.w += v.w;
        }
    }
    float inv = (deg > 0) ? 1.0f / (float)deg : 0.f;
    acc.x *= inv; acc.y *= inv; acc.z *= inv; acc.w *= inv;
    reinterpret_cast<float4*>(g_mean + (size_t)warp * D)[lane] = acc;
    if (lane == 0) g_deg[warp] = deg;
}

// ---------------------------------------------------------------------------
// Fused GEMM epilogue (word): out = relu(M_ww W1^T + m1 b1 + M_dw W2^T + m2 b2)
// ---------------------------------------------------------------------------
#define WT_PITCH 132
#define SMEM_WORD_FLOATS (2 * 128 * WT_PITCH + 2 * 64 * 128 + 128)
#define SMEM_DOC_FLOATS  (128 * WT_PITCH + 64 * 128 + 64)

__global__ __launch_bounds__(256) void gemm_word_kernel(
    const float* __restrict__ W1, const float* __restrict__ b1g,
    const float* __restrict__ W2, const float* __restrict__ b2g,
    float* __restrict__ out)
{
    extern __shared__ float sm[];
    float* Wt1 = sm;                       // 128 * 132
    float* Wt2 = Wt1 + 128 * WT_PITCH;
    float* A1  = Wt2 + 128 * WT_PITCH;     // 64 * 128
    float* A2  = A1 + 64 * 128;
    float* m1s = A2 + 64 * 128;            // 64
    float* m2s = m1s + 64;

    int tid  = threadIdx.x;
    int lane = tid & 31;
    int wr   = tid >> 5;
    int row0 = blockIdx.x * 64;

    if (tid < 64) {
        int row = row0 + tid;
        int d1 = (row < N_WORD) ? g_deg[row] : 0;
        int d2 = (row < N_WORD) ? g_deg[N_WORD + row] : 0;
        m1s[tid] = d1 > 0 ? 1.f : 0.f;
        m2s[tid] = d2 > 0 ? 1.f : 0.f;
    }
    for (int idx = tid; idx < 128 * 128; idx += 256) {
        int j = idx >> 7, k = idx & 127;
        Wt1[k * WT_PITCH + j] = W1[idx];
        Wt2[k * WT_PITCH + j] = W2[idx];
    }
    const float* M1 = g_mean;                                   // seg0
    const float* M2 = g_mean + (size_t)N_WORD * D;              // seg1
    for (int idx = tid; idx < 64 * 128; idx += 256) {
        int r = idx >> 7;
        int row = row0 + r;
        float v1 = 0.f, v2 = 0.f;
        if (row < N_WORD) {
            int k = idx & 127;
            v1 = M1[(size_t)row * D + k];
            v2 = M2[(size_t)row * D + k];
        }
        A1[idx] = v1;
        A2[idx] = v2;
    }
    __syncthreads();

    float acc[8][4];
    #pragma unroll
    for (int i = 0; i < 8; i++)
        #pragma unroll
        for (int c = 0; c < 4; c++) acc[i][c] = 0.f;

    const float* Ap = A1 + wr * 8 * 128;
    const float* Wp = Wt1;
    #pragma unroll 1
    for (int pass = 0; pass < 2; pass++) {
        #pragma unroll 2
        for (int k = 0; k < 128; k += 4) {
            float4 b0 = *reinterpret_cast<const float4*>(&Wp[(k + 0) * WT_PITCH + lane * 4]);
            float4 b1 = *reinterpret_cast<const float4*>(&Wp[(k + 1) * WT_PITCH + lane * 4]);
            float4 b2 = *reinterpret_cast<const float4*>(&Wp[(k + 2) * WT_PITCH + lane * 4]);
            float4 b3 = *reinterpret_cast<const float4*>(&Wp[(k + 3) * WT_PITCH + lane * 4]);
            #pragma unroll
            for (int i = 0; i < 8; i++) {
                float4 a = *reinterpret_cast<const float4*>(&Ap[i * 128 + k]); // broadcast
                acc[i][0] += a.x * b0.x + a.y * b1.x + a.z * b2.x + a.w * b3.x;
                acc[i][1] += a.x * b0.y + a.y * b1.y + a.z * b2.y + a.w * b3.y;
                acc[i][2] += a.x * b0.z + a.y * b1.z + a.z * b2.z + a.w * b3.z;
                acc[i][3] += a.x * b0.w + a.y * b1.w + a.z * b2.w + a.w * b3.w;
            }
        }
        Ap = A2 + wr * 8 * 128;
        Wp = Wt2;
    }

    float4 bias1 = *reinterpret_cast<const float4*>(&b1g[lane * 4]);
    float4 bias2 = *reinterpret_cast<const float4*>(&b2g[lane * 4]);
    #pragma unroll
    for (int i = 0; i < 8; i++) {
        int r = wr * 8 + i;
        int row = row0 + r;
        if (row < N_WORD) {
            float mm1 = m1s[r], mm2 = m2s[r];
            float4 o;
            o.x = fmaxf(acc[i][0] + mm1 * bias1.x + mm2 * bias2.x, 0.f);
            o.y = fmaxf(acc[i][1] + mm1 * bias1.y + mm2 * bias2.y, 0.f);
            o.z = fmaxf(acc[i][2] + mm1 * bias1.z + mm2 * bias2.z, 0.f);
            o.w = fmaxf(acc[i][3] + mm1 * bias1.w + mm2 * bias2.w, 0.f);
            *reinterpret_cast<float4*>(&out[(size_t)row * D + lane * 4]) = o;
        }
    }
}

__global__ __launch_bounds__(256) void gemm_doc_kernel(
    const float* __restrict__ W1, const float* __restrict__ b1g,
    float* __restrict__ out)
{
    extern __shared__ float sm[];
    float* Wt1 = sm;                       // 128 * 132
    float* A1  = Wt1 + 128 * WT_PITCH;     // 64 * 128
    float* m1s = A1 + 64 * 128;            // 64

    int tid  = threadIdx.x;
    int lane = tid & 31;
    int wr   = tid >> 5;
    int row0 = blockIdx.x * 64;

    if (tid < 64) {
        int row = row0 + tid;
        int d1 = (row < N_DOC) ? g_deg[2 * N_WORD + row] : 0;
        m1s[tid] = d1 > 0 ? 1.f : 0.f;
    }
    for (int idx = tid; idx < 128 * 128; idx += 256) {
        int j = idx >> 7, k = idx & 127;
        Wt1[k * WT_PITCH + j] = W1[idx];
    }
    const float* M1 = g_mean + (size_t)2 * N_WORD * D;          // seg2
    for (int idx = tid; idx < 64 * 128; idx += 256) {
        int r = idx >> 7;
        int row = row0 + r;
        float v1 = 0.f;
        if (row < N_DOC) {
            int k = idx & 127;
            v1 = M1[(size_t)row * D + k];
        }
        A1[idx] = v1;
    }
    __syncthreads();

    float acc[8][4];
    #pragma unroll
    for (int i = 0; i < 8; i++)
        #pragma unroll
        for (int c = 0; c < 4; c++) acc[i][c] = 0.f;

    const float* Ap = A1 + wr * 8 * 128;
    #pragma unroll 2
    for (int k = 0; k < 128; k += 4) {
        float4 b0 = *reinterpret_cast<const float4*>(&Wt1[(k + 0) * WT_PITCH + lane * 4]);
        float4 b1 = *reinterpret_cast<const float4*>(&Wt1[(k + 1) * WT_PITCH + lane * 4]);
        float4 b2 = *reinterpret_cast<const float4*>(&Wt1[(k + 2) * WT_PITCH + lane * 4]);
        float4 b3 = *reinterpret_cast<const float4*>(&Wt1[(k + 3) * WT_PITCH + lane * 4]);
        #pragma unroll
        for (int i = 0; i < 8; i++) {
            float4 a = *reinterpret_cast<const float4*>(&Ap[i * 128 + k]);
            acc[i][0] += a.x * b0.x + a.y * b1.x + a.z * b2.x + a.w * b3.x;
            acc[i][1] += a.x * b0.y + a.y * b1.y + a.z * b2.y + a.w * b3.y;
            acc[i][2] += a.x * b0.z + a.y * b1.z + a.z * b2.z + a.w * b3.z;
            acc[i][3] += a.x * b0.w + a.y * b1.w + a.z * b2.w + a.w * b3.w;
        }
    }

    float4 bias1 = *reinterpret_cast<const float4*>(&b1g[lane * 4]);
    #pragma unroll
    for (int i = 0; i < 8; i++) {
        int r = wr * 8 + i;
        int row = row0 + r;
        if (row < N_DOC) {
            float mm1 = m1s[r];
            float4 o;
            o.x = fmaxf(acc[i][0] + mm1 * bias1.x, 0.f);
            o.y = fmaxf(acc[i][1] + mm1 * bias1.y, 0.f);
            o.z = fmaxf(acc[i][2] + mm1 * bias1.z, 0.f);
            o.w = fmaxf(acc[i][3] + mm1 * bias1.w, 0.f);
            *reinterpret_cast<float4*>(&out[(size_t)row * D + lane * 4]) = o;
        }
    }
}

// ---------------------------------------------------------------------------
// Launch
// ---------------------------------------------------------------------------
extern "C" void kernel_launch(void* const* d_in, const int* in_sizes, int n_in,
                              void* d_out, int out_size)
{
    const float* h_word = (const float*)d_in[0];
    const float* h_doc  = (const float*)d_in[1];
    const float* W_ww   = (const float*)d_in[2];
    const float* b_ww   = (const float*)d_in[3];
    const float* W_wd   = (const float*)d_in[4];
    const float* b_wd   = (const float*)d_in[5];
    const float* W_dw   = (const float*)d_in[6];
    const float* b_dw   = (const float*)d_in[7];
    const int* src_ww = (const int*)d_in[8];
    const int* dst_ww = (const int*)d_in[9];
    const int* src_wd = (const int*)d_in[10];
    const int* dst_wd = (const int*)d_in[11];
    const int* src_dw = (const int*)d_in[12];
    const int* dst_dw = (const int*)d_in[13];
    float* out = (float*)d_out;

    int E_ww = in_sizes[8];
    int E_wd = in_sizes[10];
    int E_dw = in_sizes[12];
    int Etot = E_ww + E_dw + E_wd;

    size_t smem_word = SMEM_WORD_FLOATS * sizeof(float);
    size_t smem_doc  = SMEM_DOC_FLOATS  * sizeof(float);
    cudaFuncSetAttribute(gemm_word_kernel, cudaFuncAttributeMaxDynamicSharedMemorySize, (int)smem_word);
    cudaFuncSetAttribute(gemm_doc_kernel,  cudaFuncAttributeMaxDynamicSharedMemorySize, (int)smem_doc);

    // CSR build: seg0=ww (dst word), seg1=dw (dst word), seg2=wd (dst doc)
    zero_counts_kernel<<<(NSEG + 511) / 512, 512>>>();
    hist_kernel<<<(E_ww + 511) / 512, 512>>>(dst_ww, E_ww, 0);
    hist_kernel<<<(E_dw + 511) / 512, 512>>>(dst_dw, E_dw, N_WORD);
    hist_kernel<<<(E_wd + 511) / 512, 512>>>(dst_wd, E_wd, 2 * N_WORD);

    scan_block_kernel<<<NBLK_SCAN, SCAN_B>>>();
    scan_top_kernel<<<1, SCAN_B>>>();
    scan_finish_kernel<<<(NSEG + 511) / 512, 512>>>(Etot);

    fill_kernel<<<(E_ww + 511) / 512, 512>>>(src_ww, dst_ww, E_ww, 0);
    fill_kernel<<<(E_dw + 511) / 512, 512>>>(src_dw, dst_dw, E_dw, N_WORD);
    fill_kernel<<<(E_wd + 511) / 512, 512>>>(src_wd, dst_wd, E_wd, 2 * N_WORD);

    // Aggregate: one warp per dst node across all 3 segments
    agg_kernel<<<(NSEG * 32 + 255) / 256, 256>>>(h_word, h_doc);

    // Fused GEMM + bias-mask + relu
    gemm_word_kernel<<<(N_WORD + 63) / 64, 256, smem_word>>>(W_ww, b_ww, W_dw, b_dw, out);
    gemm_doc_kernel<<<(N_DOC + 63) / 64, 256, smem_doc>>>(W_wd, b_wd, out + (size_t)N_WORD * D);
}

// round 6
// speedup vs baseline: 4.0637x; 1.6570x over previous
#include <cuda_runtime.h>
#include <cuda_bf16.h>
#include <cstddef>
#include <cstdint>

#define N_WORD 50000
#define N_DOC  50000
#define D      128
#define NSEG   150000          // seg0: ww->word, seg1: dw->word, seg2: wd->doc
#define EMAX   1900000
#define SCAN_B 512
#define NBLK_SCAN ((NSEG + SCAN_B - 1) / SCAN_B)   // 293

// ---------------------------------------------------------------------------
// Scratch
// ---------------------------------------------------------------------------
__device__ int   g_counts[NSEG];
__device__ int   g_scan_local[NSEG];
__device__ int   g_blocksum[NBLK_SCAN];
__device__ int   g_blockoff[NBLK_SCAN];
__device__ int   g_row_ptr[NSEG + 1];
__device__ int   g_cursor[NSEG];
__device__ int   g_epos[EMAX];
__device__ float g_mean[(size_t)NSEG * D];
__device__ int   g_deg[NSEG];

// ---------------------------------------------------------------------------
// CSR build (unchanged — measured near-floor)
// ---------------------------------------------------------------------------
__global__ void zero_counts_kernel() {
    int i = blockIdx.x * blockDim.x + threadIdx.x;
    if (i < NSEG) g_counts[i] = 0;
}

__global__ __launch_bounds__(512) void hist_kernel(const int* __restrict__ dst,
                                                   int E, int segbase) {
    int i = blockIdx.x * blockDim.x + threadIdx.x;
    if (i < E) atomicAdd(&g_counts[segbase + dst[i]], 1);
}

__global__ __launch_bounds__(SCAN_B) void scan_block_kernel() {
    __shared__ int sm[SCAN_B];
    int b = blockIdx.x, t = threadIdx.x;
    int gi = b * SCAN_B + t;
    int v = (gi < NSEG) ? g_counts[gi] : 0;
    sm[t] = v;
    __syncthreads();
    #pragma unroll
    for (int off = 1; off < SCAN_B; off <<= 1) {
        int x = (t >= off) ? sm[t - off] : 0;
        __syncthreads();
        sm[t] += x;
        __syncthreads();
    }
    if (gi < NSEG) g_scan_local[gi] = sm[t] - v;
    if (t == SCAN_B - 1) g_blocksum[b] = sm[t];
}

__global__ __launch_bounds__(SCAN_B) void scan_top_kernel() {
    __shared__ int sm[SCAN_B];
    int t = threadIdx.x;
    int v = (t < NBLK_SCAN) ? g_blocksum[t] : 0;
    sm[t] = v;
    __syncthreads();
    #pragma unroll
    for (int off = 1; off < SCAN_B; off <<= 1) {
        int x = (t >= off) ? sm[t - off] : 0;
        __syncthreads();
        sm[t] += x;
        __syncthreads();
    }
    if (t < NBLK_SCAN) g_blockoff[t] = sm[t] - v;
}

__global__ void scan_finish_kernel(int Etot) {
    int i = blockIdx.x * blockDim.x + threadIdx.x;
    if (i < NSEG) {
        int v = g_scan_local[i] + g_blockoff[i / SCAN_B];
        g_row_ptr[i] = v;
        g_cursor[i]  = v;
    }
    if (i == 0) g_row_ptr[NSEG] = Etot;
}

__global__ __launch_bounds__(512) void fill_kernel(const int* __restrict__ src,
                                                   const int* __restrict__ dst,
                                                   int E, int segbase) {
    int i = blockIdx.x * blockDim.x + threadIdx.x;
    if (i < E) {
        int p = atomicAdd(&g_cursor[segbase + dst[i]], 1);
        g_epos[p] = src[i];
    }
}

// ---------------------------------------------------------------------------
// warp-per-dst gather-reduce (unchanged)
// ---------------------------------------------------------------------------
__global__ __launch_bounds__(256) void agg_kernel(const float* __restrict__ h_word,
                                                  const float* __restrict__ h_doc) {
    int warp = (blockIdx.x * blockDim.x + threadIdx.x) >> 5;
    int lane = threadIdx.x & 31;
    if (warp >= NSEG) return;

    const float* h = (warp >= N_WORD && warp < 2 * N_WORD) ? h_doc : h_word;

    int start = g_row_ptr[warp];
    int end   = g_row_ptr[warp + 1];
    int deg   = end - start;

    float4 acc = make_float4(0.f, 0.f, 0.f, 0.f);
    for (int base = start; base < end; base += 32) {
        int n = min(32, end - base);
        int myidx = (lane < n) ? g_epos[base + lane] : 0;
        for (int j = 0; j < n; j++) {
            int s = __shfl_sync(0xFFFFFFFFu, myidx, j);
            float4 v = reinterpret_cast<const float4*>(h + (size_t)s * D)[lane];
            acc.x += v.x; acc.y += v.y; acc.z += v.z; acc.w += v.w;
        }
    }
    float inv = (deg > 0) ? 1.0f / (float)deg : 0.f;
    acc.x *= inv; acc.y *= inv; acc.z *= inv; acc.w *= inv;
    reinterpret_cast<float4*>(g_mean + (size_t)warp * D)[lane] = acc;
    if (lane == 0) g_deg[warp] = deg;
}

// ---------------------------------------------------------------------------
// mma.sync bf16x3 GEMM:  out = relu( sum_p mean_p @ W_p^T + mask_p*b_p )
// Block tile: M=128 x N=128, K=128 per pass. 8 warps as 4x2 (M x N),
// each warp 32x64 via m16n8k16 HMMA. fp32 split into hi/lo bf16;
// accumulate Ah*Bh + Ah*Bl + Al*Bh in fp32.
// B fragment: W stored [n][k] row-major == exactly the ldmatrix (non-trans)
// fragment the mma B operand wants (lane l: n=l/4, k=2(l%4)) -> plain ldsm4.
// ---------------------------------------------------------------------------
#define GT 256
#define OFF_AH   0
#define OFF_AL   32768
#define OFF_BH   65536
#define OFF_BL   98304
#define OFF_BIAS 131072
#define OFF_MASK (131072 + 1024)
#define GSMEM    (131072 + 2048)

__device__ __forceinline__ uint32_t smem_u32(const void* p) {
    uint32_t a;
    asm("{ .reg .u64 t; cvta.to.shared.u64 t, %1; cvt.u32.u64 %0, t; }"
        : "=r"(a) : "l"(p));
    return a;
}

__device__ __forceinline__ uint32_t pack_hi_lo(float a, float b, uint32_t& lo) {
    __nv_bfloat16 ha = __float2bfloat16(a), hb = __float2bfloat16(b);
    __nv_bfloat16 la = __float2bfloat16(a - __bfloat162float(ha));
    __nv_bfloat16 lb = __float2bfloat16(b - __bfloat162float(hb));
    __nv_bfloat162 hp = __halves2bfloat162(ha, hb);
    __nv_bfloat162 lp = __halves2bfloat162(la, lb);
    lo = *reinterpret_cast<uint32_t*>(&lp);
    return *reinterpret_cast<uint32_t*>(&hp);
}

// Stage 128x128 fp32 row-major tile as hi/lo bf16 with 3-bit XOR swizzle.
// bf16 row = 256B = 16 chunks of 16B; chunk' = chunk ^ (row & 7).
__device__ __forceinline__ void stage_split(char* smem, int offH, int offL,
                                            const float* __restrict__ src,
                                            int rows_valid) {
    for (int idx = threadIdx.x; idx < 2048; idx += GT) {
        int row = idx >> 4, c16 = idx & 15;
        float4 v0 = make_float4(0.f, 0.f, 0.f, 0.f);
        float4 v1 = v0;
        if (row < rows_valid) {
            v0 = reinterpret_cast<const float4*>(src)[row * 32 + c16 * 2];
            v1 = reinterpret_cast<const float4*>(src)[row * 32 + c16 * 2 + 1];
        }
        uint4 hv, lv;
        hv.x = pack_hi_lo(v0.x, v0.y, lv.x);
        hv.y = pack_hi_lo(v0.z, v0.w, lv.y);
        hv.z = pack_hi_lo(v1.x, v1.y, lv.z);
        hv.w = pack_hi_lo(v1.z, v1.w, lv.w);
        uint32_t off = ((uint32_t)row << 8) + (((uint32_t)(c16 ^ (row & 7))) << 4);
        *reinterpret_cast<uint4*>(smem + offH + off) = hv;
        *reinterpret_cast<uint4*>(smem + offL + off) = lv;
    }
}

__device__ __forceinline__ void ldsm4(uint32_t* r, uint32_t a) {
    asm volatile("ldmatrix.sync.aligned.m8n8.x4.shared.b16 {%0,%1,%2,%3}, [%4];"
        : "=r"(r[0]), "=r"(r[1]), "=r"(r[2]), "=r"(r[3]) : "r"(a));
}
__device__ __forceinline__ void mma16816(float* c, const uint32_t* a,
                                         uint32_t b0, uint32_t b1) {
    asm volatile(
        "mma.sync.aligned.m16n8k16.row.col.f32.bf16.bf16.f32 "
        "{%0,%1,%2,%3}, {%4,%5,%6,%7}, {%8,%9}, {%0,%1,%2,%3};"
        : "+f"(c[0]), "+f"(c[1]), "+f"(c[2]), "+f"(c[3])
        : "r"(a[0]), "r"(a[1]), "r"(a[2]), "r"(a[3]), "r"(b0), "r"(b1));
}

__global__ void __launch_bounds__(GT, 1) gemm_mma_kernel(
    const float* __restrict__ W_ww, const float* __restrict__ b_ww,
    const float* __restrict__ W_dw, const float* __restrict__ b_dw,
    const float* __restrict__ W_wd, const float* __restrict__ b_wd,
    const float* __restrict__ mean, const int* __restrict__ deg,
    float* __restrict__ out, int nblk_word)
{
    extern __shared__ __align__(16) char smem[];
    uint32_t sb = smem_u32(smem);
    int tid  = threadIdx.x;
    int lane = tid & 31;
    int wid  = tid >> 5;
    int wm   = wid & 3;      // M warp: rows 32*wm
    int wn   = wid >> 2;     // N warp: cols 64*wn

    int  bid     = blockIdx.x;
    bool is_word = bid < nblk_word;
    int  row0    = (is_word ? bid : bid - nblk_word) * 128;
    int  nrows   = is_word ? N_WORD : N_DOC;
    int  nmat    = is_word ? 2 : 1;
    int  rows_valid = min(128, nrows - row0);

    const float* Wm[2]; const float* bm[2]; const float* Am[2]; const int* dm[2];
    if (is_word) {
        Wm[0] = W_ww; bm[0] = b_ww; Am[0] = mean + (size_t)row0 * D;                      dm[0] = deg;
        Wm[1] = W_dw; bm[1] = b_dw; Am[1] = mean + (size_t)N_WORD * D + (size_t)row0 * D; dm[1] = deg + N_WORD;
    } else {
        Wm[0] = W_wd; bm[0] = b_wd; Am[0] = mean + (size_t)2 * N_WORD * D + (size_t)row0 * D; dm[0] = deg + 2 * N_WORD;
        Wm[1] = Wm[0]; bm[1] = bm[0]; Am[1] = Am[0]; dm[1] = dm[0];
        out += (size_t)N_WORD * D;
    }

    float* sbias0 = reinterpret_cast<float*>(smem + OFF_BIAS);
    float* sbias1 = sbias0 + 128;
    float* smask0 = reinterpret_cast<float*>(smem + OFF_MASK);
    float* smask1 = smask0 + 128;
    if (tid < 128) {
        int r = row0 + tid;
        bool ok = tid < rows_valid;
        sbias0[tid] = bm[0][tid];
        sbias1[tid] = (nmat == 2) ? bm[1][tid] : 0.f;
        smask0[tid] = (ok && dm[0][r] > 0) ? 1.f : 0.f;
        smask1[tid] = (nmat == 2 && ok && dm[1][r] > 0) ? 1.f : 0.f;
    }

    float c[2][8][4];
    #pragma unroll
    for (int mi = 0; mi < 2; mi++)
        #pragma unroll
        for (int ng = 0; ng < 8; ng++)
            #pragma unroll
            for (int q = 0; q < 4; q++) c[mi][ng][q] = 0.f;

    for (int p = 0; p < nmat; p++) {
        if (p) __syncthreads();                 // prev pass done reading smem
        stage_split(smem, OFF_AH, OFF_AL, Am[p], rows_valid);
        stage_split(smem, OFF_BH, OFF_BL, Wm[p], 128);
        __syncthreads();

        #pragma unroll 1
        for (int g = 0; g < 8; g++) {
            uint32_t ah[2][4], al[2][4];
            #pragma unroll
            for (int mi = 0; mi < 2; mi++) {
                int row = (wm << 5) + (mi << 4) + (lane & 15);
                int ch  = (g << 1) + (lane >> 4);
                uint32_t off = ((uint32_t)row << 8) + ((uint32_t)(ch ^ (row & 7)) << 4);
                ldsm4(ah[mi], sb + OFF_AH + off);
                ldsm4(al[mi], sb + OFF_AL + off);
            }
            uint32_t bh[4][4], bl[4][4];
            #pragma unroll
            for (int ng = 0; ng < 4; ng++) {
                int n  = (wn << 6) + (ng << 4) + (lane & 7) + ((lane >> 4) << 3);
                int ch = (g << 1) + ((lane >> 3) & 1);
                uint32_t off = ((uint32_t)n << 8) + ((uint32_t)(ch ^ (n & 7)) << 4);
                ldsm4(bh[ng], sb + OFF_BH + off);   // non-trans: [n][k] rows ARE the B fragment
                ldsm4(bl[ng], sb + OFF_BL + off);
            }
            #pragma unroll
            for (int mi = 0; mi < 2; mi++)
                #pragma unroll
                for (int ng = 0; ng < 4; ng++) {
                    mma16816(c[mi][2 * ng],     ah[mi], bh[ng][0], bh[ng][1]);
                    mma16816(c[mi][2 * ng + 1], ah[mi], bh[ng][2], bh[ng][3]);
                    mma16816(c[mi][2 * ng],     ah[mi], bl[ng][0], bl[ng][1]);
                    mma16816(c[mi][2 * ng + 1], ah[mi], bl[ng][2], bl[ng][3]);
                    mma16816(c[mi][2 * ng],     al[mi], bh[ng][0], bh[ng][1]);
                    mma16816(c[mi][2 * ng + 1], al[mi], bh[ng][2], bh[ng][3]);
                }
        }
    }

    // epilogue: D frag lane map: c0,c1 -> (row=l/4, col=2*(l%4)+{0,1}); c2,c3 -> row+8
    int g4 = lane >> 2, t4 = lane & 3;
    #pragma unroll
    for (int mi = 0; mi < 2; mi++) {
        int rl0 = (wm << 5) + (mi << 4) + g4;
        int rl1 = rl0 + 8;
        float ma0 = smask0[rl0], mb0 = smask1[rl0];
        float ma1 = smask0[rl1], mb1 = smask1[rl1];
        bool ok0 = rl0 < rows_valid, ok1 = rl1 < rows_valid;
        float* o0 = out + (size_t)(row0 + rl0) * D;
        float* o1 = out + (size_t)(row0 + rl1) * D;
        #pragma unroll
        for (int ng = 0; ng < 8; ng++) {
            int col = (wn << 6) + (ng << 3) + (t4 << 1);
            float bb0 = sbias0[col],     bc0 = sbias1[col];
            float bb1 = sbias0[col + 1], bc1 = sbias1[col + 1];
            if (ok0) {
                float2 v;
                v.x = fmaxf(c[mi][ng][0] + ma0 * bb0 + mb0 * bc0, 0.f);
                v.y = fmaxf(c[mi][ng][1] + ma0 * bb1 + mb0 * bc1, 0.f);
                *reinterpret_cast<float2*>(o0 + col) = v;
            }
            if (ok1) {
                float2 v;
                v.x = fmaxf(c[mi][ng][2] + ma1 * bb0 + mb1 * bc0, 0.f);
                v.y = fmaxf(c[mi][ng][3] + ma1 * bb1 + mb1 * bc1, 0.f);
                *reinterpret_cast<float2*>(o1 + col) = v;
            }
        }
    }
}

// ---------------------------------------------------------------------------
// Launch
// ---------------------------------------------------------------------------
extern "C" void kernel_launch(void* const* d_in, const int* in_sizes, int n_in,
                              void* d_out, int out_size)
{
    const float* h_word = (const float*)d_in[0];
    const float* h_doc  = (const float*)d_in[1];
    const float* W_ww   = (const float*)d_in[2];
    const float* b_ww   = (const float*)d_in[3];
    const float* W_wd   = (const float*)d_in[4];
    const float* b_wd   = (const float*)d_in[5];
    const float* W_dw   = (const float*)d_in[6];
    const float* b_dw   = (const float*)d_in[7];
    const int* src_ww = (const int*)d_in[8];
    const int* dst_ww = (const int*)d_in[9];
    const int* src_wd = (const int*)d_in[10];
    const int* dst_wd = (const int*)d_in[11];
    const int* src_dw = (const int*)d_in[12];
    const int* dst_dw = (const int*)d_in[13];
    float* out = (float*)d_out;

    int E_ww = in_sizes[8];
    int E_wd = in_sizes[10];
    int E_dw = in_sizes[12];
    int Etot = E_ww + E_dw + E_wd;

    float* p_mean; int* p_deg;
    cudaGetSymbolAddress((void**)&p_mean, g_mean);
    cudaGetSymbolAddress((void**)&p_deg,  g_deg);

    cudaFuncSetAttribute(gemm_mma_kernel,
                         cudaFuncAttributeMaxDynamicSharedMemorySize, GSMEM);

    // CSR build
    zero_counts_kernel<<<(NSEG + 511) / 512, 512>>>();
    hist_kernel<<<(E_ww + 511) / 512, 512>>>(dst_ww, E_ww, 0);
    hist_kernel<<<(E_dw + 511) / 512, 512>>>(dst_dw, E_dw, N_WORD);
    hist_kernel<<<(E_wd + 511) / 512, 512>>>(dst_wd, E_wd, 2 * N_WORD);

    scan_block_kernel<<<NBLK_SCAN, SCAN_B>>>();
    scan_top_kernel<<<1, SCAN_B>>>();
    scan_finish_kernel<<<(NSEG + 511) / 512, 512>>>(Etot);

    fill_kernel<<<(E_ww + 511) / 512, 512>>>(src_ww, dst_ww, E_ww, 0);
    fill_kernel<<<(E_dw + 511) / 512, 512>>>(src_dw, dst_dw, E_dw, N_WORD);
    fill_kernel<<<(E_wd + 511) / 512, 512>>>(src_wd, dst_wd, E_wd, 2 * N_WORD);

    // Aggregate
    agg_kernel<<<(NSEG * 32 + 255) / 256, 256>>>(h_word, h_doc);

    // Tensor-core (mma.sync) GEMM + bias-mask + relu
    int nblk_word = (N_WORD + 127) / 128;
    int nblk_doc  = (N_DOC  + 127) / 128;
    gemm_mma_kernel<<<nblk_word + nblk_doc, GT, GSMEM>>>(
        W_ww, b_ww, W_dw, b_dw, W_wd, b_wd, p_mean, p_deg, out, nblk_word);
}

// round 7
// speedup vs baseline: 4.6379x; 1.1413x over previous
#include <cuda_runtime.h>
#include <cuda_bf16.h>
#include <cstddef>
#include <cstdint>

#define N_WORD 50000
#define N_DOC  50000
#define D      128
#define NSEG   150000          // seg0: ww->word, seg1: dw->word, seg2: wd->doc
#define EMAX   1900000
#define SCAN_B 512
#define NBLK_SCAN ((NSEG + SCAN_B - 1) / SCAN_B)   // 293

// ---------------------------------------------------------------------------
// Scratch
// ---------------------------------------------------------------------------
__device__ int   g_counts[NSEG];
__device__ int   g_scan_local[NSEG];
__device__ int   g_blocksum[NBLK_SCAN];
__device__ int   g_blockoff[NBLK_SCAN];
__device__ int   g_row_ptr[NSEG + 1];
__device__ int   g_cursor[NSEG];
__device__ int   g_epos[EMAX];
__device__ float g_mean[(size_t)NSEG * D];
__device__ int   g_deg[NSEG];

// ---------------------------------------------------------------------------
// CSR build — merged single-pass kernels over all 3 edge lists
// ---------------------------------------------------------------------------
__global__ void zero_counts_kernel() {
    int i = blockIdx.x * blockDim.x + threadIdx.x;
    if (i < NSEG) g_counts[i] = 0;
}

__global__ __launch_bounds__(512) void hist_all_kernel(
    const int* __restrict__ d0, const int* __restrict__ d1,
    const int* __restrict__ d2, int E0, int E1, int E2)
{
    int i = blockIdx.x * blockDim.x + threadIdx.x;
    int dst, base;
    if (i < E0)                { dst = d0[i];            base = 0; }
    else if (i < E0 + E1)      { dst = d1[i - E0];       base = N_WORD; }
    else if (i < E0 + E1 + E2) { dst = d2[i - E0 - E1];  base = 2 * N_WORD; }
    else return;
    atomicAdd(&g_counts[base + dst], 1);
}

__global__ __launch_bounds__(SCAN_B) void scan_block_kernel() {
    __shared__ int sm[SCAN_B];
    int b = blockIdx.x, t = threadIdx.x;
    int gi = b * SCAN_B + t;
    int v = (gi < NSEG) ? g_counts[gi] : 0;
    sm[t] = v;
    __syncthreads();
    #pragma unroll
    for (int off = 1; off < SCAN_B; off <<= 1) {
        int x = (t >= off) ? sm[t - off] : 0;
        __syncthreads();
        sm[t] += x;
        __syncthreads();
    }
    if (gi < NSEG) g_scan_local[gi] = sm[t] - v;
    if (t == SCAN_B - 1) g_blocksum[b] = sm[t];
}

__global__ __launch_bounds__(SCAN_B) void scan_top_kernel() {
    __shared__ int sm[SCAN_B];
    int t = threadIdx.x;
    int v = (t < NBLK_SCAN) ? g_blocksum[t] : 0;
    sm[t] = v;
    __syncthreads();
    #pragma unroll
    for (int off = 1; off < SCAN_B; off <<= 1) {
        int x = (t >= off) ? sm[t - off] : 0;
        __syncthreads();
        sm[t] += x;
        __syncthreads();
    }
    if (t < NBLK_SCAN) g_blockoff[t] = sm[t] - v;
}

__global__ void scan_finish_kernel(int Etot) {
    int i = blockIdx.x * blockDim.x + threadIdx.x;
    if (i < NSEG) {
        int v = g_scan_local[i] + g_blockoff[i / SCAN_B];
        g_row_ptr[i] = v;
        g_cursor[i]  = v;
    }
    if (i == 0) g_row_ptr[NSEG] = Etot;
}

__global__ __launch_bounds__(512) void fill_all_kernel(
    const int* __restrict__ s0, const int* __restrict__ d0,
    const int* __restrict__ s1, const int* __restrict__ d1,
    const int* __restrict__ s2, const int* __restrict__ d2,
    int E0, int E1, int E2)
{
    int i = blockIdx.x * blockDim.x + threadIdx.x;
    int src, dst, base;
    if (i < E0)                { src = s0[i];           dst = d0[i];           base = 0; }
    else if (i < E0 + E1)      { int j = i - E0;        src = s1[j]; dst = d1[j]; base = N_WORD; }
    else if (i < E0 + E1 + E2) { int j = i - E0 - E1;   src = s2[j]; dst = d2[j]; base = 2 * N_WORD; }
    else return;
    int p = atomicAdd(&g_cursor[base + dst], 1);
    g_epos[p] = src;
}

// ---------------------------------------------------------------------------
// warp-per-dst gather-reduce (unchanged — at L2 floor)
// ---------------------------------------------------------------------------
__global__ __launch_bounds__(256) void agg_kernel(const float* __restrict__ h_word,
                                                  const float* __restrict__ h_doc) {
    int warp = (blockIdx.x * blockDim.x + threadIdx.x) >> 5;
    int lane = threadIdx.x & 31;
    if (warp >= NSEG) return;

    const float* h = (warp >= N_WORD && warp < 2 * N_WORD) ? h_doc : h_word;

    int start = g_row_ptr[warp];
    int end   = g_row_ptr[warp + 1];
    int deg   = end - start;

    float4 acc = make_float4(0.f, 0.f, 0.f, 0.f);
    for (int base = start; base < end; base += 32) {
        int n = min(32, end - base);
        int myidx = (lane < n) ? g_epos[base + lane] : 0;
        for (int j = 0; j < n; j++) {
            int s = __shfl_sync(0xFFFFFFFFu, myidx, j);
            float4 v = reinterpret_cast<const float4*>(h + (size_t)s * D)[lane];
            acc.x += v.x; acc.y += v.y; acc.z += v.z; acc.w += v.w;
        }
    }
    float inv = (deg > 0) ? 1.0f / (float)deg : 0.f;
    acc.x *= inv; acc.y *= inv; acc.z *= inv; acc.w *= inv;
    reinterpret_cast<float4*>(g_mean + (size_t)warp * D)[lane] = acc;
    if (lane == 0) g_deg[warp] = deg;
}

// ---------------------------------------------------------------------------
// mma.sync bf16x3 GEMM, M=64 x N=128 tile (2 CTAs/SM for stage/MMA overlap).
// 8 warps as 2(M) x 4(N); warp tile 32x32. fp32 split hi/lo bf16; accumulate
// Ah*Bh + Ah*Bl + Al*Bh in fp32. B = W[n][k] row-major == non-trans ldmatrix
// fragment for the mma B operand.
// ---------------------------------------------------------------------------
#define GT 256
#define OFF_AH   0
#define OFF_AL   16384
#define OFF_BH   32768
#define OFF_BL   65536
#define OFF_BIAS 98304
#define OFF_MASK (98304 + 1024)
#define GSMEM    (98304 + 1536)

__device__ __forceinline__ uint32_t smem_u32(const void* p) {
    uint32_t a;
    asm("{ .reg .u64 t; cvta.to.shared.u64 t, %1; cvt.u32.u64 %0, t; }"
        : "=r"(a) : "l"(p));
    return a;
}

__device__ __forceinline__ uint32_t pack_hi_lo(float a, float b, uint32_t& lo) {
    __nv_bfloat16 ha = __float2bfloat16(a), hb = __float2bfloat16(b);
    __nv_bfloat16 la = __float2bfloat16(a - __bfloat162float(ha));
    __nv_bfloat16 lb = __float2bfloat16(b - __bfloat162float(hb));
    __nv_bfloat162 hp = __halves2bfloat162(ha, hb);
    __nv_bfloat162 lp = __halves2bfloat162(la, lb);
    lo = *reinterpret_cast<uint32_t*>(&lp);
    return *reinterpret_cast<uint32_t*>(&hp);
}

// Stage rows x 128 fp32 row-major as hi/lo bf16, 3-bit XOR swizzle
// (bf16 row = 256B = 16 chunks of 16B; chunk' = chunk ^ (row & 7)).
__device__ __forceinline__ void stage_split(char* smem, int offH, int offL,
                                            const float* __restrict__ src,
                                            int rows, int rows_valid) {
    for (int idx = threadIdx.x; idx < rows * 16; idx += GT) {
        int row = idx >> 4, c16 = idx & 15;
        float4 v0 = make_float4(0.f, 0.f, 0.f, 0.f);
        float4 v1 = v0;
        if (row < rows_valid) {
            v0 = reinterpret_cast<const float4*>(src)[row * 32 + c16 * 2];
            v1 = reinterpret_cast<const float4*>(src)[row * 32 + c16 * 2 + 1];
        }
        uint4 hv, lv;
        hv.x = pack_hi_lo(v0.x, v0.y, lv.x);
        hv.y = pack_hi_lo(v0.z, v0.w, lv.y);
        hv.z = pack_hi_lo(v1.x, v1.y, lv.z);
        hv.w = pack_hi_lo(v1.z, v1.w, lv.w);
        uint32_t off = ((uint32_t)row << 8) + (((uint32_t)(c16 ^ (row & 7))) << 4);
        *reinterpret_cast<uint4*>(smem + offH + off) = hv;
        *reinterpret_cast<uint4*>(smem + offL + off) = lv;
    }
}

__device__ __forceinline__ void ldsm4(uint32_t* r, uint32_t a) {
    asm volatile("ldmatrix.sync.aligned.m8n8.x4.shared.b16 {%0,%1,%2,%3}, [%4];"
        : "=r"(r[0]), "=r"(r[1]), "=r"(r[2]), "=r"(r[3]) : "r"(a));
}
__device__ __forceinline__ void mma16816(float* c, const uint32_t* a,
                                         uint32_t b0, uint32_t b1) {
    asm volatile(
        "mma.sync.aligned.m16n8k16.row.col.f32.bf16.bf16.f32 "
        "{%0,%1,%2,%3}, {%4,%5,%6,%7}, {%8,%9}, {%0,%1,%2,%3};"
        : "+f"(c[0]), "+f"(c[1]), "+f"(c[2]), "+f"(c[3])
        : "r"(a[0]), "r"(a[1]), "r"(a[2]), "r"(a[3]), "r"(b0), "r"(b1));
}

__global__ void __launch_bounds__(GT, 2) gemm_mma_kernel(
    const float* __restrict__ W_ww, const float* __restrict__ b_ww,
    const float* __restrict__ W_dw, const float* __restrict__ b_dw,
    const float* __restrict__ W_wd, const float* __restrict__ b_wd,
    const float* __restrict__ mean, const int* __restrict__ deg,
    float* __restrict__ out, int nblk_word)
{
    extern __shared__ __align__(16) char smem[];
    uint32_t sb = smem_u32(smem);
    int tid  = threadIdx.x;
    int lane = tid & 31;
    int wid  = tid >> 5;
    int wm   = wid & 1;      // M warp: rows 32*wm
    int wn   = wid >> 1;     // N warp: cols 32*wn

    int  bid     = blockIdx.x;
    bool is_word = bid < nblk_word;
    int  row0    = (is_word ? bid : bid - nblk_word) * 64;
    int  nrows   = is_word ? N_WORD : N_DOC;
    int  nmat    = is_word ? 2 : 1;
    int  rows_valid = min(64, nrows - row0);

    const float* Wm[2]; const float* bm[2]; const float* Am[2]; const int* dm[2];
    if (is_word) {
        Wm[0] = W_ww; bm[0] = b_ww; Am[0] = mean + (size_t)row0 * D;                      dm[0] = deg;
        Wm[1] = W_dw; bm[1] = b_dw; Am[1] = mean + (size_t)N_WORD * D + (size_t)row0 * D; dm[1] = deg + N_WORD;
    } else {
        Wm[0] = W_wd; bm[0] = b_wd; Am[0] = mean + (size_t)2 * N_WORD * D + (size_t)row0 * D; dm[0] = deg + 2 * N_WORD;
        Wm[1] = Wm[0]; bm[1] = bm[0]; Am[1] = Am[0]; dm[1] = dm[0];
        out += (size_t)N_WORD * D;
    }

    float* sbias0 = reinterpret_cast<float*>(smem + OFF_BIAS);
    float* sbias1 = sbias0 + 128;
    float* smask0 = reinterpret_cast<float*>(smem + OFF_MASK);
    float* smask1 = smask0 + 64;
    if (tid < 128) {
        sbias0[tid] = bm[0][tid];
        sbias1[tid] = (nmat == 2) ? bm[1][tid] : 0.f;
    }
    if (tid < 64) {
        int r = row0 + tid;
        bool ok = tid < rows_valid;
        smask0[tid] = (ok && dm[0][r] > 0) ? 1.f : 0.f;
        smask1[tid] = (nmat == 2 && ok && dm[1][r] > 0) ? 1.f : 0.f;
    }

    float c[2][4][4];
    #pragma unroll
    for (int mi = 0; mi < 2; mi++)
        #pragma unroll
        for (int ng = 0; ng < 4; ng++)
            #pragma unroll
            for (int q = 0; q < 4; q++) c[mi][ng][q] = 0.f;

    for (int p = 0; p < nmat; p++) {
        if (p) __syncthreads();                 // prev pass done reading smem
        stage_split(smem, OFF_AH, OFF_AL, Am[p], 64, rows_valid);
        stage_split(smem, OFF_BH, OFF_BL, Wm[p], 128, 128);
        __syncthreads();

        #pragma unroll 1
        for (int g = 0; g < 8; g++) {
            uint32_t ah[2][4], al[2][4];
            #pragma unroll
            for (int mi = 0; mi < 2; mi++) {
                int row = (wm << 5) + (mi << 4) + (lane & 15);
                int ch  = (g << 1) + (lane >> 4);
                uint32_t off = ((uint32_t)row << 8) + ((uint32_t)(ch ^ (row & 7)) << 4);
                ldsm4(ah[mi], sb + OFF_AH + off);
                ldsm4(al[mi], sb + OFF_AL + off);
            }
            uint32_t bh[2][4], bl[2][4];
            #pragma unroll
            for (int ng = 0; ng < 2; ng++) {
                int n  = (wn << 5) + (ng << 4) + (lane & 7) + ((lane >> 4) << 3);
                int ch = (g << 1) + ((lane >> 3) & 1);
                uint32_t off = ((uint32_t)n << 8) + ((uint32_t)(ch ^ (n & 7)) << 4);
                ldsm4(bh[ng], sb + OFF_BH + off);   // non-trans: [n][k] rows are the B frag
                ldsm4(bl[ng], sb + OFF_BL + off);
            }
            #pragma unroll
            for (int mi = 0; mi < 2; mi++)
                #pragma unroll
                for (int ng = 0; ng < 2; ng++) {
                    mma16816(c[mi][2 * ng],     ah[mi], bh[ng][0], bh[ng][1]);
                    mma16816(c[mi][2 * ng + 1], ah[mi], bh[ng][2], bh[ng][3]);
                    mma16816(c[mi][2 * ng],     ah[mi], bl[ng][0], bl[ng][1]);
                    mma16816(c[mi][2 * ng + 1], ah[mi], bl[ng][2], bl[ng][3]);
                    mma16816(c[mi][2 * ng],     al[mi], bh[ng][0], bh[ng][1]);
                    mma16816(c[mi][2 * ng + 1], al[mi], bh[ng][2], bh[ng][3]);
                }
        }
    }

    // epilogue: D frag: c0,c1 -> (row=l/4, col=2*(l%4)+{0,1}); c2,c3 -> row+8
    int g4 = lane >> 2, t4 = lane & 3;
    #pragma unroll
    for (int mi = 0; mi < 2; mi++) {
        int rl0 = (wm << 5) + (mi << 4) + g4;
        int rl1 = rl0 + 8;
        float ma0 = smask0[rl0], mb0 = smask1[rl0];
        float ma1 = smask0[rl1], mb1 = smask1[rl1];
        bool ok0 = rl0 < rows_valid, ok1 = rl1 < rows_valid;
        float* o0 = out + (size_t)(row0 + rl0) * D;
        float* o1 = out + (size_t)(row0 + rl1) * D;
        #pragma unroll
        for (int ng = 0; ng < 4; ng++) {
            int col = (wn << 5) + (ng << 3) + (t4 << 1);
            float bb0 = sbias0[col],     bc0 = sbias1[col];
            float bb1 = sbias0[col + 1], bc1 = sbias1[col + 1];
            if (ok0) {
                float2 v;
                v.x = fmaxf(c[mi][ng][0] + ma0 * bb0 + mb0 * bc0, 0.f);
                v.y = fmaxf(c[mi][ng][1] + ma0 * bb1 + mb0 * bc1, 0.f);
                *reinterpret_cast<float2*>(o0 + col) = v;
            }
            if (ok1) {
                float2 v;
                v.x = fmaxf(c[mi][ng][2] + ma1 * bb0 + mb1 * bc0, 0.f);
                v.y = fmaxf(c[mi][ng][3] + ma1 * bb1 + mb1 * bc1, 0.f);
                *reinterpret_cast<float2*>(o1 + col) = v;
            }
        }
    }
}

// ---------------------------------------------------------------------------
// Launch
// ---------------------------------------------------------------------------
extern "C" void kernel_launch(void* const* d_in, const int* in_sizes, int n_in,
                              void* d_out, int out_size)
{
    const float* h_word = (const float*)d_in[0];
    const float* h_doc  = (const float*)d_in[1];
    const float* W_ww   = (const float*)d_in[2];
    const float* b_ww   = (const float*)d_in[3];
    const float* W_wd   = (const float*)d_in[4];
    const float* b_wd   = (const float*)d_in[5];
    const float* W_dw   = (const float*)d_in[6];
    const float* b_dw   = (const float*)d_in[7];
    const int* src_ww = (const int*)d_in[8];
    const int* dst_ww = (const int*)d_in[9];
    const int* src_wd = (const int*)d_in[10];
    const int* dst_wd = (const int*)d_in[11];
    const int* src_dw = (const int*)d_in[12];
    const int* dst_dw = (const int*)d_in[13];
    float* out = (float*)d_out;

    int E_ww = in_sizes[8];
    int E_wd = in_sizes[10];
    int E_dw = in_sizes[12];
    int Etot = E_ww + E_dw + E_wd;

    float* p_mean; int* p_deg;
    cudaGetSymbolAddress((void**)&p_mean, g_mean);
    cudaGetSymbolAddress((void**)&p_deg,  g_deg);

    cudaFuncSetAttribute(gemm_mma_kernel,
                         cudaFuncAttributeMaxDynamicSharedMemorySize, GSMEM);

    // CSR build: seg0=ww, seg1=dw, seg2=wd — one pass per phase over all edges
    zero_counts_kernel<<<(NSEG + 511) / 512, 512>>>();
    hist_all_kernel<<<(Etot + 511) / 512, 512>>>(dst_ww, dst_dw, dst_wd,
                                                 E_ww, E_dw, E_wd);
    scan_block_kernel<<<NBLK_SCAN, SCAN_B>>>();
    scan_top_kernel<<<1, SCAN_B>>>();
    scan_finish_kernel<<<(NSEG + 511) / 512, 512>>>(Etot);
    fill_all_kernel<<<(Etot + 511) / 512, 512>>>(src_ww, dst_ww, src_dw, dst_dw,
                                                 src_wd, dst_wd, E_ww, E_dw, E_wd);

    // Aggregate: one warp per dst node across all 3 segments
    agg_kernel<<<(NSEG * 32 + 255) / 256, 256>>>(h_word, h_doc);

    // Tensor-core (mma.sync) GEMM + bias-mask + relu; M=64 tiles, 2 CTAs/SM
    int nblk_word = (N_WORD + 63) / 64;
    int nblk_doc  = (N_DOC  + 63) / 64;
    gemm_mma_kernel<<<nblk_word + nblk_doc, GT, GSMEM>>>(
        W_ww, b_ww, W_dw, b_dw, W_wd, b_wd, p_mean, p_deg, out, nblk_word);
}